// round 14
// baseline (speedup 1.0000x reference)
#include <cuda_runtime.h>
#include <cuda_fp16.h>
#include <math_constants.h>
#include <cstdint>

// Problem constants
#define Bq 4
#define Ss 1024
#define Ee 1024
#define Hh 16
#define DKk 64

// ---------------------------------------------------------------------------
// Device scratch (no allocations allowed)
// ---------------------------------------------------------------------------
__device__ __half g_Qh[(size_t)Bq * Ss * Ee];            // 8 MiB
__device__ __half g_Kh[(size_t)Bq * Ss * Ee];            // 8 MiB
__device__ __half g_Ph[(size_t)Bq * Hh * Ss * Ss];       // 128 MiB unnormalized exp [b][q][h][k]
__device__ float  g_inv[(size_t)Bq * Ss * Hh];           // 256 KiB per-row 1/sum
__device__ __half g_xh[(size_t)Bq * Ss * Ee];            // 8 MiB
__device__ __half g_Wqh[Ee * Ee], g_Wkh[Ee * Ee], g_Woh[Ee * Ee];

// ---------------------------------------------------------------------------
// PTX helpers (base compute_103 ISA only)
// ---------------------------------------------------------------------------
__device__ __forceinline__ uint32_t smem_u32(const void* p) {
    uint32_t a;
    asm("{ .reg .u64 t; cvta.to.shared.u64 t, %1; cvt.u32.u64 %0, t; }"
        : "=r"(a) : "l"(p));
    return a;
}
__device__ __forceinline__ void cp_async16(uint32_t saddr, const void* gaddr) {
    asm volatile("cp.async.cg.shared.global [%0], [%1], 16;"
                 :: "r"(saddr), "l"(gaddr) : "memory");
}
#define CP_COMMIT() asm volatile("cp.async.commit_group;" ::: "memory")
#define CP_WAIT(n)  asm volatile("cp.async.wait_group %0;" :: "n"(n) : "memory")

__device__ __forceinline__ void ldmat4(uint32_t& r0, uint32_t& r1,
                                       uint32_t& r2, uint32_t& r3, uint32_t addr) {
    asm volatile("ldmatrix.sync.aligned.m8n8.x4.shared.b16 {%0,%1,%2,%3}, [%4];"
                 : "=r"(r0), "=r"(r1), "=r"(r2), "=r"(r3) : "r"(addr));
}
__device__ __forceinline__ void mma_f16(float* c, const uint32_t* a, const uint32_t* b) {
    asm volatile(
        "mma.sync.aligned.m16n8k16.row.col.f32.f16.f16.f32 "
        "{%0,%1,%2,%3}, {%4,%5,%6,%7}, {%8,%9}, {%0,%1,%2,%3};"
        : "+f"(c[0]), "+f"(c[1]), "+f"(c[2]), "+f"(c[3])
        : "r"(a[0]), "r"(a[1]), "r"(a[2]), "r"(a[3]), "r"(b[0]), "r"(b[1]));
}

// ---------------------------------------------------------------------------
// FP16 GEMM-NT:  C = A @ B^T + bias; 128x128 tile, BK=64, NSTAGE=3,
// 256 threads (8 warps 2x4), 2 CTAs/SM.  (Round-10 proven config.)
// blockIdx.z == 1 -> (B2, bias2, Ch2).  half_out: 1 -> half Ch, 0 -> fp32 Cf.
// inv != nullptr: multiply acc by inv[row] before bias (deferred softmax norm).
// ---------------------------------------------------------------------------
#define BMt 128
#define BNt 128
#define BKt 64
#define NSTAGE 3
#define TILEB (128 * 128)
#define STAGE_BYTES (2 * TILEB)
#define GEMM_SMEM (NSTAGE * STAGE_BYTES)

__global__ __launch_bounds__(256, 2)
void gemm_f16(const __half* __restrict__ A, const __half* __restrict__ B,
              const float* __restrict__ bias, float* __restrict__ Cf,
              __half* __restrict__ Ch,
              const __half* __restrict__ B2, const float* __restrict__ bias2,
              __half* __restrict__ Ch2, int half_out,
              const float* __restrict__ inv) {
    extern __shared__ char sm[];
    __shared__ float s_bias[BNt];

    const int tid  = threadIdx.x;
    const int lane = tid & 31;
    const int wid  = tid >> 5;
    const int warp_m = wid >> 2;   // 0..1
    const int warp_n = wid & 3;    // 0..3
    const int bm = blockIdx.y * BMt;
    const int bn = blockIdx.x * BNt;

    if (blockIdx.z == 1) { B = B2; bias = bias2; Ch = Ch2; }

    if (tid < BNt) s_bias[tid] = bias[bn + tid];

    const uint32_t smb = smem_u32(sm);

    auto load_stage = [&](int c) {
        const int k0 = c * BKt;
        const uint32_t stg = smb + (c % NSTAGE) * STAGE_BYTES;
#pragma unroll
        for (int t = 0; t < 8; ++t) {
            const int idx = t * 256 + tid;
            const int region = idx >> 10;
            const int w = idx & 1023;
            const int r = w >> 3, cc = w & 7;
            const uint32_t so = stg + region * TILEB + r * 128
                              + ((cc ^ (r & 7)) << 4);
            const __half* src = region ? (B + (size_t)(bn + r) * Ee)
                                       : (A + (size_t)(bm + r) * Ee);
            cp_async16(so, src + k0 + cc * 8);
        }
        CP_COMMIT();
    };

    const int nk = Ee / BKt;   // 16
    for (int c = 0; c < NSTAGE - 1; ++c) load_stage(c);

    float acc[4][4][4];
#pragma unroll
    for (int mi = 0; mi < 4; ++mi)
#pragma unroll
        for (int ni = 0; ni < 4; ++ni)
#pragma unroll
            for (int j = 0; j < 4; ++j) acc[mi][ni][j] = 0.0f;

    const int tsub = (((lane >> 3) & 1) << 3) + (lane & 7);
    const int chof = lane >> 4;

    for (int c = 0; c < nk; ++c) {
        CP_WAIT(NSTAGE - 2);
        __syncthreads();
        if (c + NSTAGE - 1 < nk) load_stage(c + NSTAGE - 1);
        else CP_COMMIT();

        const uint32_t stgA = smb + (c % NSTAGE) * STAGE_BYTES;
        const uint32_t stgB = stgA + TILEB;
#pragma unroll
        for (int ks = 0; ks < 4; ++ks) {
            const int chunk = 2 * ks + chof;
            uint32_t a[4][4], b[4][2];
#pragma unroll
            for (int mi = 0; mi < 4; ++mi) {
                const int row = warp_m * 64 + mi * 16 + tsub;
                ldmat4(a[mi][0], a[mi][1], a[mi][2], a[mi][3],
                       stgA + row * 128 + ((chunk ^ (row & 7)) << 4));
            }
#pragma unroll
            for (int nf = 0; nf < 2; ++nf) {
                const int row = warp_n * 32 + nf * 16 + tsub;
                uint32_t q0, q1, q2, q3;
                ldmat4(q0, q1, q2, q3,
                       stgB + row * 128 + ((chunk ^ (row & 7)) << 4));
                b[nf * 2 + 0][0] = q0; b[nf * 2 + 0][1] = q2;
                b[nf * 2 + 1][0] = q1; b[nf * 2 + 1][1] = q3;
            }
#pragma unroll
            for (int mi = 0; mi < 4; ++mi)
#pragma unroll
                for (int ni = 0; ni < 4; ++ni)
                    mma_f16(acc[mi][ni], a[mi], b[ni]);
        }
    }

    // ---- epilogue (optionally scaled by inv[row]) ----
    const int r0 = lane >> 2;
    const int c0 = (lane & 3) * 2;
#pragma unroll
    for (int mi = 0; mi < 4; ++mi) {
        const int gr0 = bm + warp_m * 64 + mi * 16 + r0;
        const float s0 = inv ? inv[gr0]     : 1.0f;
        const float s1 = inv ? inv[gr0 + 8] : 1.0f;
#pragma unroll
        for (int ni = 0; ni < 4; ++ni) {
            const int lc = warp_n * 32 + ni * 8 + c0;
            const int gc = bn + lc;
            const float b0 = s_bias[lc], b1 = s_bias[lc + 1];
            if (half_out) {
                __half2 h0, h1;
                h0.x = __float2half_rn(acc[mi][ni][0] + b0);
                h0.y = __float2half_rn(acc[mi][ni][1] + b1);
                h1.x = __float2half_rn(acc[mi][ni][2] + b0);
                h1.y = __float2half_rn(acc[mi][ni][3] + b1);
                *(__half2*)&Ch[(size_t)gr0 * Ee + gc]       = h0;
                *(__half2*)&Ch[(size_t)(gr0 + 8) * Ee + gc] = h1;
            } else {
                float2 v0, v1;
                v0.x = acc[mi][ni][0] * s0 + b0; v0.y = acc[mi][ni][1] * s0 + b1;
                v1.x = acc[mi][ni][2] * s1 + b0; v1.y = acc[mi][ni][3] * s1 + b1;
                *(float2*)&Cf[(size_t)gr0 * Ee + gc]       = v0;
                *(float2*)&Cf[(size_t)(gr0 + 8) * Ee + gc] = v1;
            }
        }
    }
}

// ---------------------------------------------------------------------------
// Scores + mask + UNNORMALIZED exp -> g_Ph; per-row 1/sum -> g_inv.
// Per CTA: one (b,h), 64 q-rows. K streamed ONCE (8 chunks, 3-stage cp.async);
// per chunk, B-frags loaded once and reused by 4 q-subtiles (contraction d=64
// completes within a chunk -> no cross-chunk accumulators).
// 256 threads, smem 56 KB, low regs -> 3 CTAs/SM.
// ---------------------------------------------------------------------------
#define AQR 64
#define KST_B 16384
#define QOFF (3 * KST_B)                   // 49152
#define APRE_SMEM (3 * KST_B + 8192)       // 57344

__global__ __launch_bounds__(256, 3)
void attn_pre(const int* __restrict__ mask) {
    extern __shared__ char sm[];
    __shared__ float s_red[4][16][8];

    const int tid  = threadIdx.x;
    const int lane = tid & 31;
    const int wid  = tid >> 5;          // 0..7 : 16 cols per 128-chunk
    const int b  = blockIdx.y >> 4;
    const int h  = blockIdx.y & 15;
    const int q0 = blockIdx.x * AQR;

    const __half* Qg = g_Qh + ((size_t)(b * Ss + q0)) * Ee + h * DKk;
    const __half* Kg = g_Kh + (size_t)b * Ss * Ee + h * DKk;

    const uint32_t smb = smem_u32(sm);
    const int tsub = (((lane >> 3) & 1) << 3) + (lane & 7);
    const int chof = lane >> 4;

    // Q strip: 64 rows x 64 halves (128B rows, swizzle c^(r&7)) — 512 xfers
#pragma unroll
    for (int t = 0; t < 2; ++t) {
        const int idx = t * 256 + tid;
        const int r = idx >> 3, c = idx & 7;
        cp_async16(smb + QOFF + r * 128 + ((c ^ (r & 7)) << 4),
                   Qg + (size_t)r * Ee + c * 8);
    }
    auto loadK = [&](int ch) {
        const uint32_t stg = smb + (ch % 3) * KST_B;
#pragma unroll
        for (int t = 0; t < 4; ++t) {
            const int idx = t * 256 + tid;
            const int r = idx >> 3, c = idx & 7;
            cp_async16(stg + r * 128 + ((c ^ (r & 7)) << 4),
                       Kg + (size_t)(ch * 128 + r) * Ee + c * 8);
        }
    };
    loadK(0); CP_COMMIT();     // group 0: Q + K chunk 0
    loadK(1); CP_COMMIT();

    float sums[4][2];
#pragma unroll
    for (int qs = 0; qs < 4; ++qs) { sums[qs][0] = 0.0f; sums[qs][1] = 0.0f; }

    const int r0 = lane >> 2;          // 0..7
    const int r1 = r0 + 8;
    const int pc0 = wid * 16 + (lane & 3) * 2;   // col within 128-chunk

#pragma unroll
    for (int ch = 0; ch < 8; ++ch) {
        CP_WAIT(1);
        __syncthreads();
        if (ch + 2 < 8) { loadK(ch + 2); CP_COMMIT(); } else CP_COMMIT();

        const uint32_t stg = smb + (ch % 3) * KST_B;

        // B-fragments for this chunk (reused by all 4 q-subtiles)
        uint32_t bfr[4][2][2];
#pragma unroll
        for (int s = 0; s < 4; ++s) {
            const int rowB = wid * 16 + tsub;
            const int cc = 2 * s + chof;
            uint32_t v0, v1, v2, v3;
            ldmat4(v0, v1, v2, v3, stg + rowB * 128 + ((cc ^ (rowB & 7)) << 4));
            bfr[s][0][0] = v0; bfr[s][0][1] = v2;
            bfr[s][1][0] = v1; bfr[s][1][1] = v3;
        }

#pragma unroll
        for (int qs = 0; qs < 4; ++qs) {
            float acc[2][4];
#pragma unroll
            for (int p = 0; p < 2; ++p)
#pragma unroll
                for (int j = 0; j < 4; ++j) acc[p][j] = 0.0f;

#pragma unroll
            for (int s = 0; s < 4; ++s) {
                const int row = qs * 16 + tsub;
                const int cc = 2 * s + chof;
                uint32_t afr[4];
                ldmat4(afr[0], afr[1], afr[2], afr[3],
                       smb + QOFF + row * 128 + ((cc ^ (row & 7)) << 4));
                mma_f16(acc[0], afr, bfr[s][0]);
                mma_f16(acc[1], afr, bfr[s][1]);
            }

            // mask -> exp (unnormalized) -> accumulate sums -> store
            const size_t qr0 = (size_t)(b * Ss + q0 + qs * 16 + r0);
            const size_t qr1 = (size_t)(b * Ss + q0 + qs * 16 + r1);
            const int* mrow0 = mask + qr0 * Ss;
            const int* mrow1 = mask + qr1 * Ss;
            __half* P0 = g_Ph + (qr0 * Hh + h) * Ss;
            __half* P1 = g_Ph + (qr1 * Hh + h) * Ss;
#pragma unroll
            for (int p = 0; p < 2; ++p) {
                const int n = ch * 128 + p * 8 + pc0;
                const int2 m0 = *(const int2*)(mrow0 + n);
                const int2 m1 = *(const int2*)(mrow1 + n);
                float* v = acc[p];
                v[0] = m0.x ? __expf(v[0] * 0.125f) : 0.0f;
                v[1] = m0.y ? __expf(v[1] * 0.125f) : 0.0f;
                v[2] = m1.x ? __expf(v[2] * 0.125f) : 0.0f;
                v[3] = m1.y ? __expf(v[3] * 0.125f) : 0.0f;
                sums[qs][0] += v[0] + v[1];
                sums[qs][1] += v[2] + v[3];
                __half2 o0, o1;
                o0.x = __float2half_rn(v[0]); o0.y = __float2half_rn(v[1]);
                o1.x = __float2half_rn(v[2]); o1.y = __float2half_rn(v[3]);
                *(__half2*)(P0 + n) = o0;
                *(__half2*)(P1 + n) = o1;
            }
        }
    }

    // ---- row-sum reduction -> g_inv ----
#pragma unroll
    for (int qs = 0; qs < 4; ++qs) {
        float s0 = sums[qs][0], s1 = sums[qs][1];
        s0 += __shfl_xor_sync(0xffffffffu, s0, 1);
        s0 += __shfl_xor_sync(0xffffffffu, s0, 2);
        s1 += __shfl_xor_sync(0xffffffffu, s1, 1);
        s1 += __shfl_xor_sync(0xffffffffu, s1, 2);
        if ((lane & 3) == 0) {
            s_red[qs][r0][wid] = s0;
            s_red[qs][r1][wid] = s1;
        }
    }
    __syncthreads();
    if (tid < 64) {
        const int qs = tid >> 4, row = tid & 15;
        float t = 0.0f;
#pragma unroll
        for (int w = 0; w < 8; ++w) t += s_red[qs][row][w];
        g_inv[((size_t)(b * Ss + q0 + qs * 16 + row)) * Hh + h] = 1.0f / t;
    }
}

// ---------------------------------------------------------------------------
// Merged fp32 -> fp16 (rn) conversion: grid.y 0..3 = quarters of x, 4..6 = W's.
// ---------------------------------------------------------------------------
__global__ void conv_f16_all(const float4* __restrict__ x, __half2* __restrict__ xh,
                             const float4* __restrict__ wq, __half2* __restrict__ wqh,
                             const float4* __restrict__ wk, __half2* __restrict__ wkh,
                             const float4* __restrict__ wo, __half2* __restrict__ woh) {
    const int seg = blockIdx.y;
    const int i = blockIdx.x * blockDim.x + threadIdx.x;
    const float4* s; __half2* d;
    if (seg < 4)      { s = x  + (size_t)seg * 262144; d = xh  + (size_t)seg * 524288; }
    else if (seg == 4){ s = wq; d = wqh; }
    else if (seg == 5){ s = wk; d = wkh; }
    else              { s = wo; d = woh; }
    const float4 v = s[i];
    __half2 h0, h1;
    h0.x = __float2half_rn(v.x); h0.y = __float2half_rn(v.y);
    h1.x = __float2half_rn(v.z); h1.y = __float2half_rn(v.w);
    d[i * 2 + 0] = h0;
    d[i * 2 + 1] = h1;
}

// ---------------------------------------------------------------------------
extern "C" void kernel_launch(void* const* d_in, const int* in_sizes, int n_in,
                              void* d_out, int out_size) {
    const float* x   = (const float*)d_in[0];
    const int*   msk = (const int*)  d_in[1];
    const float* Wq  = (const float*)d_in[2];
    const float* bq  = (const float*)d_in[3];
    const float* Wk  = (const float*)d_in[4];
    const float* bk  = (const float*)d_in[5];
    // d_in[6], d_in[7] = Wv, bv : unused (reference discards V)
    const float* Wo  = (const float*)d_in[8];
    const float* bo  = (const float*)d_in[9];
    float* out = (float*)d_out;

    __half *qh, *kh, *ph, *xh, *wqh, *wkh, *woh;
    float* invp;
    cudaGetSymbolAddress((void**)&qh,  g_Qh);
    cudaGetSymbolAddress((void**)&kh,  g_Kh);
    cudaGetSymbolAddress((void**)&ph,  g_Ph);
    cudaGetSymbolAddress((void**)&invp, g_inv);
    cudaGetSymbolAddress((void**)&xh,  g_xh);
    cudaGetSymbolAddress((void**)&wqh, g_Wqh);
    cudaGetSymbolAddress((void**)&wkh, g_Wkh);
    cudaGetSymbolAddress((void**)&woh, g_Woh);

    cudaFuncSetAttribute(gemm_f16,
                         cudaFuncAttributeMaxDynamicSharedMemorySize, GEMM_SMEM);
    cudaFuncSetAttribute(attn_pre,
                         cudaFuncAttributeMaxDynamicSharedMemorySize, APRE_SMEM);

    // 0) fp32 -> fp16 conversion (one launch)
    {
        dim3 grid(1024, 7);
        conv_f16_all<<<grid, 256>>>((const float4*)x,  (__half2*)xh,
                                    (const float4*)Wq, (__half2*)wqh,
                                    (const float4*)Wk, (__half2*)wkh,
                                    (const float4*)Wo, (__half2*)woh);
    }

    // 1) Q + K projections in ONE launch (z=0 -> Q, z=1 -> K), fp16 outputs
    {
        dim3 grid(Ee / BNt, (Bq * Ss) / BMt, 2);   // (8, 32, 2)
        gemm_f16<<<grid, 256, GEMM_SMEM>>>(xh, wqh, bq, nullptr, qh,
                                           wkh, bk, kh, 1, nullptr);
    }

    // 2) Scores + mask + unnormalized exp -> g_Ph; 1/rowsum -> g_inv
    {
        dim3 grid(Ss / AQR, Bq * Hh);              // (16, 64)
        attn_pre<<<grid, 256, APRE_SMEM>>>(msk);
    }

    // 3) Output projection with deferred normalization:
    //    out = (P_unnorm @ Wo^T) * inv[row] + bo
    {
        const int M = Bq * Ss * Hh;                // 65536
        dim3 grid(Ee / BNt, M / BMt, 1);           // (8, 512)
        gemm_f16<<<grid, 256, GEMM_SMEM>>>(ph, woh, bo, out, nullptr,
                                           woh, bo, nullptr, 0, invp);
    }
}

// round 15
// speedup vs baseline: 1.6860x; 1.6860x over previous
#include <cuda_runtime.h>
#include <cuda_fp16.h>
#include <math_constants.h>
#include <cstdint>

// Problem constants
#define Bq 4
#define Ss 1024
#define Ee 1024
#define Hh 16
#define DKk 64

// ---------------------------------------------------------------------------
// Device scratch (no allocations allowed)
// ---------------------------------------------------------------------------
__device__ __half g_Qh[(size_t)Bq * Ss * Ee];            // 8 MiB
__device__ __half g_Kh[(size_t)Bq * Ss * Ee];            // 8 MiB
__device__ __half g_Ph[(size_t)Bq * Hh * Ss * Ss];       // 128 MiB probs [b][q][h][k]
__device__ __half g_xh[(size_t)Bq * Ss * Ee];            // 8 MiB
__device__ __half g_Wqh[Ee * Ee], g_Wkh[Ee * Ee], g_Woh[Ee * Ee];

// ---------------------------------------------------------------------------
// PTX helpers (base compute_103 ISA only)
// ---------------------------------------------------------------------------
__device__ __forceinline__ uint32_t smem_u32(const void* p) {
    uint32_t a;
    asm("{ .reg .u64 t; cvta.to.shared.u64 t, %1; cvt.u32.u64 %0, t; }"
        : "=r"(a) : "l"(p));
    return a;
}
__device__ __forceinline__ void cp_async16(uint32_t saddr, const void* gaddr) {
    asm volatile("cp.async.cg.shared.global [%0], [%1], 16;"
                 :: "r"(saddr), "l"(gaddr) : "memory");
}
#define CP_COMMIT() asm volatile("cp.async.commit_group;" ::: "memory")
#define CP_WAIT(n)  asm volatile("cp.async.wait_group %0;" :: "n"(n) : "memory")

__device__ __forceinline__ void ldmat4(uint32_t& r0, uint32_t& r1,
                                       uint32_t& r2, uint32_t& r3, uint32_t addr) {
    asm volatile("ldmatrix.sync.aligned.m8n8.x4.shared.b16 {%0,%1,%2,%3}, [%4];"
                 : "=r"(r0), "=r"(r1), "=r"(r2), "=r"(r3) : "r"(addr));
}
__device__ __forceinline__ void mma_f16(float* c, const uint32_t* a, const uint32_t* b) {
    asm volatile(
        "mma.sync.aligned.m16n8k16.row.col.f32.f16.f16.f32 "
        "{%0,%1,%2,%3}, {%4,%5,%6,%7}, {%8,%9}, {%0,%1,%2,%3};"
        : "+f"(c[0]), "+f"(c[1]), "+f"(c[2]), "+f"(c[3])
        : "r"(a[0]), "r"(a[1]), "r"(a[2]), "r"(a[3]), "r"(b[0]), "r"(b[1]));
}

// ---------------------------------------------------------------------------
// FP16 GEMM-NT:  C[M,N] = A[M,K=1024] @ B[N,K]^T + bias[N]; all ld = 1024.
// 128x128 block tile, BK=64 (128B rows, 8x16B chunks, swizzle cc ^ (r&7)),
// 3-stage cp.async pipeline, 256 threads (8 warps 2x4), 2 CTAs/SM.
// (Round-8/10/11 proven config: ~368us on the output GEMM.)
// ---------------------------------------------------------------------------
#define BMt 128
#define BNt 128
#define BKt 64
#define NSTAGE 3
#define TILEB (128 * 128)              // one operand tile: 16 KiB
#define STAGE_BYTES (2 * TILEB)        // A + B: 32 KiB
#define GEMM_SMEM (NSTAGE * STAGE_BYTES)

__global__ __launch_bounds__(256, 2)
void gemm_f16(const __half* __restrict__ A, const __half* __restrict__ B,
              const float* __restrict__ bias, float* __restrict__ Cf,
              __half* __restrict__ Ch,
              const __half* __restrict__ B2, const float* __restrict__ bias2,
              __half* __restrict__ Ch2, int half_out) {
    extern __shared__ char sm[];
    __shared__ float s_bias[BNt];

    const int tid  = threadIdx.x;
    const int lane = tid & 31;
    const int wid  = tid >> 5;
    const int warp_m = wid >> 2;   // 0..1
    const int warp_n = wid & 3;    // 0..3
    const int bm = blockIdx.y * BMt;
    const int bn = blockIdx.x * BNt;

    if (blockIdx.z == 1) { B = B2; bias = bias2; Ch = Ch2; }

    if (tid < BNt) s_bias[tid] = bias[bn + tid];

    const uint32_t smb = smem_u32(sm);

    auto load_stage = [&](int c) {
        const int k0 = c * BKt;
        const uint32_t stg = smb + (c % NSTAGE) * STAGE_BYTES;
#pragma unroll
        for (int t = 0; t < 8; ++t) {
            const int idx = t * 256 + tid;          // 0..2047
            const int region = idx >> 10;           // 0=A, 1=B
            const int w = idx & 1023;
            const int r = w >> 3, cc = w & 7;
            const uint32_t so = stg + region * TILEB + r * 128
                              + ((cc ^ (r & 7)) << 4);
            const __half* src = region ? (B + (size_t)(bn + r) * Ee)
                                       : (A + (size_t)(bm + r) * Ee);
            cp_async16(so, src + k0 + cc * 8);
        }
        CP_COMMIT();
    };

    const int nk = Ee / BKt;   // 16
    for (int c = 0; c < NSTAGE - 1; ++c) load_stage(c);

    float acc[4][4][4];
#pragma unroll
    for (int mi = 0; mi < 4; ++mi)
#pragma unroll
        for (int ni = 0; ni < 4; ++ni)
#pragma unroll
            for (int j = 0; j < 4; ++j) acc[mi][ni][j] = 0.0f;

    const int tsub = (((lane >> 3) & 1) << 3) + (lane & 7);  // row within 16-row frag
    const int chof = lane >> 4;                               // 16B chunk within k16

    for (int c = 0; c < nk; ++c) {
        CP_WAIT(NSTAGE - 2);
        __syncthreads();
        if (c + NSTAGE - 1 < nk) load_stage(c + NSTAGE - 1);
        else CP_COMMIT();

        const uint32_t stgA = smb + (c % NSTAGE) * STAGE_BYTES;
        const uint32_t stgB = stgA + TILEB;
#pragma unroll
        for (int ks = 0; ks < 4; ++ks) {
            const int chunk = 2 * ks + chof;
            uint32_t a[4][4], b[4][2];
#pragma unroll
            for (int mi = 0; mi < 4; ++mi) {
                const int row = warp_m * 64 + mi * 16 + tsub;
                ldmat4(a[mi][0], a[mi][1], a[mi][2], a[mi][3],
                       stgA + row * 128 + ((chunk ^ (row & 7)) << 4));
            }
#pragma unroll
            for (int nf = 0; nf < 2; ++nf) {
                const int row = warp_n * 32 + nf * 16 + tsub;
                uint32_t q0, q1, q2, q3;
                ldmat4(q0, q1, q2, q3,
                       stgB + row * 128 + ((chunk ^ (row & 7)) << 4));
                b[nf * 2 + 0][0] = q0; b[nf * 2 + 0][1] = q2;
                b[nf * 2 + 1][0] = q1; b[nf * 2 + 1][1] = q3;
            }
#pragma unroll
            for (int mi = 0; mi < 4; ++mi)
#pragma unroll
                for (int ni = 0; ni < 4; ++ni)
                    mma_f16(acc[mi][ni], a[mi], b[ni]);
        }
    }

    // ---- epilogue ----
    const int r0 = lane >> 2;
    const int c0 = (lane & 3) * 2;
#pragma unroll
    for (int mi = 0; mi < 4; ++mi) {
        const int gr0 = bm + warp_m * 64 + mi * 16 + r0;
#pragma unroll
        for (int ni = 0; ni < 4; ++ni) {
            const int lc = warp_n * 32 + ni * 8 + c0;
            const int gc = bn + lc;
            const float b0 = s_bias[lc], b1 = s_bias[lc + 1];
            if (half_out) {
                __half2 h0, h1;
                h0.x = __float2half_rn(acc[mi][ni][0] + b0);
                h0.y = __float2half_rn(acc[mi][ni][1] + b1);
                h1.x = __float2half_rn(acc[mi][ni][2] + b0);
                h1.y = __float2half_rn(acc[mi][ni][3] + b1);
                *(__half2*)&Ch[(size_t)gr0 * Ee + gc]       = h0;
                *(__half2*)&Ch[(size_t)(gr0 + 8) * Ee + gc] = h1;
            } else {
                float2 v0, v1;
                v0.x = acc[mi][ni][0] + b0; v0.y = acc[mi][ni][1] + b1;
                v1.x = acc[mi][ni][2] + b0; v1.y = acc[mi][ni][3] + b1;
                *(float2*)&Cf[(size_t)gr0 * Ee + gc]       = v0;
                *(float2*)&Cf[(size_t)(gr0 + 8) * Ee + gc] = v1;
            }
        }
    }
}

// ---------------------------------------------------------------------------
// Fused scores + mask + softmax: per CTA = one (b,h), 16 q-rows, full 1024 cols.
// 16-row tile -> acc 64 regs/thread -> 2 CTAs/SM. Max-free softmax.
// 8 warps, warp w covers cols [w*16, w*16+16) within each 128-col chunk.
// (Round-11 proven config: best total 537.7us.)
// ---------------------------------------------------------------------------
#define FQR 16
#define FSM_A 0
#define FSM_B 2048
#define KCH_B 16384
#define FUSED_SMEM (2048 + 3 * KCH_B)      // 51200

__global__ __launch_bounds__(256, 2)
void attn_fused(const int* __restrict__ mask) {
    extern __shared__ char sm[];
    __shared__ float s_red[FQR][8];

    const int tid  = threadIdx.x;
    const int lane = tid & 31;
    const int warp_n = tid >> 5;        // 0..7
    const int b  = blockIdx.y >> 4;
    const int h  = blockIdx.y & 15;
    const int q0 = blockIdx.x * FQR;

    const __half* Ag = g_Qh + ((size_t)(b * Ss + q0)) * Ee + h * DKk;
    const __half* Bg = g_Kh + (size_t)b * Ss * Ee + h * DKk;

    const uint32_t smb = smem_u32(sm);
    const int tsub = (((lane >> 3) & 1) << 3) + (lane & 7);
    const int chof = lane >> 4;      // 16B chunk within k16 pair

    // ---- loaders (rows = 64 halves = 128B = 8 x 16B chunks, swizzle c^(r&7)) ----
    if (tid < FQR * 8) {   // A: 16 rows x 8 chunks = 128 transfers
        const int r = tid >> 3, c = tid & 7;
        cp_async16(smb + FSM_A + r * 128 + ((c ^ (r & 7)) << 4),
                   Ag + (size_t)r * Ee + c * 8);
    }
    auto loadB = [&](int ch) {
        const uint32_t stg = smb + FSM_B + (ch % 3) * KCH_B;
#pragma unroll
        for (int t = 0; t < 4; ++t) {
            const int idx = t * 256 + tid;
            const int r = idx >> 3, c = idx & 7;
            cp_async16(stg + r * 128 + ((c ^ (r & 7)) << 4),
                       Bg + (size_t)(ch * 128 + r) * Ee + c * 8);
        }
    };

    loadB(0); CP_COMMIT();      // group: A + B chunk 0
    loadB(1); CP_COMMIT();

    float acc[8][2][4];
#pragma unroll
    for (int ch = 0; ch < 8; ++ch)
#pragma unroll
        for (int p = 0; p < 2; ++p)
#pragma unroll
            for (int j = 0; j < 4; ++j) acc[ch][p][j] = 0.0f;

    uint32_t afr[4][4];

#pragma unroll
    for (int ch = 0; ch < 8; ++ch) {
        CP_WAIT(1);
        __syncthreads();
        if (ch + 2 < 8) { loadB(ch + 2); CP_COMMIT(); } else CP_COMMIT();

        if (ch == 0) {
#pragma unroll
            for (int s = 0; s < 4; ++s) {
                const int row = tsub;               // 16 q-rows
                const int cc = 2 * s + chof;
                ldmat4(afr[s][0], afr[s][1], afr[s][2], afr[s][3],
                       smb + FSM_A + row * 128 + ((cc ^ (row & 7)) << 4));
            }
        }

        const uint32_t stg = smb + FSM_B + (ch % 3) * KCH_B;
#pragma unroll
        for (int s = 0; s < 4; ++s) {
            const int cc = 2 * s + chof;
            const int rowB = warp_n * 16 + tsub;
            uint32_t q0r, q1r, q2r, q3r;
            ldmat4(q0r, q1r, q2r, q3r,
                   stg + rowB * 128 + ((cc ^ (rowB & 7)) << 4));
            uint32_t be[2] = {q0r, q2r};
            uint32_t bo[2] = {q1r, q3r};
            mma_f16(acc[ch][0], afr[s], be);
            mma_f16(acc[ch][1], afr[s], bo);
        }
    }

    // ---- single sweep: mask -> exp -> sum (rows r0, r1 = r0+8) ----
    const int r0 = lane >> 2;
    const int r1 = r0 + 8;
    const int ncol0 = warp_n * 16 + (lane & 3) * 2;
    const int* mrow0 = mask + ((size_t)(b * Ss + q0 + r0)) * Ss;
    const int* mrow1 = mask + ((size_t)(b * Ss + q0 + r1)) * Ss;

    float sum0 = 0.0f, sum1 = 0.0f;
#pragma unroll
    for (int ch = 0; ch < 8; ++ch)
#pragma unroll
        for (int p = 0; p < 2; ++p) {
            const int n = ch * 128 + p * 8 + ncol0;
            const int2 m0 = *(const int2*)(mrow0 + n);
            const int2 m1 = *(const int2*)(mrow1 + n);
            float* v = acc[ch][p];
            v[0] = m0.x ? __expf(v[0] * 0.125f) : 0.0f;
            v[1] = m0.y ? __expf(v[1] * 0.125f) : 0.0f;
            v[2] = m1.x ? __expf(v[2] * 0.125f) : 0.0f;
            v[3] = m1.y ? __expf(v[3] * 0.125f) : 0.0f;
            sum0 += v[0] + v[1];
            sum1 += v[2] + v[3];
        }
    sum0 += __shfl_xor_sync(0xffffffffu, sum0, 1);
    sum0 += __shfl_xor_sync(0xffffffffu, sum0, 2);
    sum1 += __shfl_xor_sync(0xffffffffu, sum1, 1);
    sum1 += __shfl_xor_sync(0xffffffffu, sum1, 2);
    if ((lane & 3) == 0) { s_red[r0][warp_n] = sum0; s_red[r1][warp_n] = sum1; }
    __syncthreads();
    const float inv0 = 1.0f / (s_red[r0][0] + s_red[r0][1] + s_red[r0][2] + s_red[r0][3]
                             + s_red[r0][4] + s_red[r0][5] + s_red[r0][6] + s_red[r0][7]);
    const float inv1 = 1.0f / (s_red[r1][0] + s_red[r1][1] + s_red[r1][2] + s_red[r1][3]
                             + s_red[r1][4] + s_red[r1][5] + s_red[r1][6] + s_red[r1][7]);

    __half* P0 = g_Ph + ((size_t)((b * Ss + q0 + r0) * Hh + h)) * Ss;
    __half* P1 = g_Ph + ((size_t)((b * Ss + q0 + r1) * Hh + h)) * Ss;
#pragma unroll
    for (int ch = 0; ch < 8; ++ch)
#pragma unroll
        for (int p = 0; p < 2; ++p) {
            const int n = ch * 128 + p * 8 + ncol0;
            const float* v = acc[ch][p];
            __half2 o0, o1;
            o0.x = __float2half_rn(v[0] * inv0); o0.y = __float2half_rn(v[1] * inv0);
            o1.x = __float2half_rn(v[2] * inv1); o1.y = __float2half_rn(v[3] * inv1);
            *(__half2*)(P0 + n) = o0;
            *(__half2*)(P1 + n) = o1;
        }
}

// ---------------------------------------------------------------------------
// Merged fp32 -> fp16 (rn) conversion. grid.y 0..3 = quarters of x, 4..6 = W's.
// Each segment = 262144 float4; each thread converts 2 float4s (MLP=2).
// ---------------------------------------------------------------------------
__global__ void conv_f16_all(const float4* __restrict__ x, __half2* __restrict__ xh,
                             const float4* __restrict__ wq, __half2* __restrict__ wqh,
                             const float4* __restrict__ wk, __half2* __restrict__ wkh,
                             const float4* __restrict__ wo, __half2* __restrict__ woh) {
    const int seg = blockIdx.y;
    const int i0 = blockIdx.x * blockDim.x + threadIdx.x;
    const float4* s; __half2* d;
    if (seg < 4)      { s = x  + (size_t)seg * 262144; d = xh  + (size_t)seg * 524288; }
    else if (seg == 4){ s = wq; d = wqh; }
    else if (seg == 5){ s = wk; d = wkh; }
    else              { s = wo; d = woh; }
#pragma unroll
    for (int t = 0; t < 2; ++t) {
        const int i = i0 + t * 131072;
        const float4 v = s[i];
        __half2 h0, h1;
        h0.x = __float2half_rn(v.x); h0.y = __float2half_rn(v.y);
        h1.x = __float2half_rn(v.z); h1.y = __float2half_rn(v.w);
        d[i * 2 + 0] = h0;
        d[i * 2 + 1] = h1;
    }
}

// ---------------------------------------------------------------------------
extern "C" void kernel_launch(void* const* d_in, const int* in_sizes, int n_in,
                              void* d_out, int out_size) {
    const float* x   = (const float*)d_in[0];
    const int*   msk = (const int*)  d_in[1];
    const float* Wq  = (const float*)d_in[2];
    const float* bq  = (const float*)d_in[3];
    const float* Wk  = (const float*)d_in[4];
    const float* bk  = (const float*)d_in[5];
    // d_in[6], d_in[7] = Wv, bv : unused (reference discards V)
    const float* Wo  = (const float*)d_in[8];
    const float* bo  = (const float*)d_in[9];
    float* out = (float*)d_out;

    __half *qh, *kh, *ph, *xh, *wqh, *wkh, *woh;
    cudaGetSymbolAddress((void**)&qh,  g_Qh);
    cudaGetSymbolAddress((void**)&kh,  g_Kh);
    cudaGetSymbolAddress((void**)&ph,  g_Ph);
    cudaGetSymbolAddress((void**)&xh,  g_xh);
    cudaGetSymbolAddress((void**)&wqh, g_Wqh);
    cudaGetSymbolAddress((void**)&wkh, g_Wkh);
    cudaGetSymbolAddress((void**)&woh, g_Woh);

    cudaFuncSetAttribute(gemm_f16,
                         cudaFuncAttributeMaxDynamicSharedMemorySize, GEMM_SMEM);
    cudaFuncSetAttribute(attn_fused,
                         cudaFuncAttributeMaxDynamicSharedMemorySize, FUSED_SMEM);

    // 0) fp32 -> fp16 conversion (one launch, 2 float4/thread)
    {
        dim3 grid(512, 7);
        conv_f16_all<<<grid, 256>>>((const float4*)x,  (__half2*)xh,
                                    (const float4*)Wq, (__half2*)wqh,
                                    (const float4*)Wk, (__half2*)wkh,
                                    (const float4*)Wo, (__half2*)woh);
    }

    // 1) Q + K projections in ONE launch (z=0 -> Q, z=1 -> K), fp16 outputs
    {
        dim3 grid(Ee / BNt, (Bq * Ss) / BMt, 2);   // (8, 32, 2)
        gemm_f16<<<grid, 256, GEMM_SMEM>>>(xh, wqh, bq, nullptr, qh,
                                           wkh, bk, kh, 1);
    }

    // 2) Fused scores + mask + softmax -> g_Ph (fp16), 2 CTAs/SM
    {
        dim3 grid(Ss / FQR, Bq * Hh);              // (64, 64)
        attn_fused<<<grid, 256, FUSED_SMEM>>>(msk);
    }

    // 3) Output projection: P[65536,1024] @ Wo^T + bo -> fp32 out
    {
        const int M = Bq * Ss * Hh;                // 65536
        dim3 grid(Ee / BNt, M / BMt, 1);           // (8, 512)
        gemm_f16<<<grid, 256, GEMM_SMEM>>>(ph, woh, bo, out, nullptr,
                                           woh, bo, nullptr, 0);
    }
}

// round 16
// speedup vs baseline: 1.7112x; 1.0149x over previous
#include <cuda_runtime.h>
#include <cuda_fp16.h>
#include <math_constants.h>
#include <cstdint>

// Problem constants
#define Bq 4
#define Ss 1024
#define Ee 1024
#define Hh 16
#define DKk 64

// ---------------------------------------------------------------------------
// Device scratch (no allocations allowed)
// ---------------------------------------------------------------------------
__device__ __half g_Qh[(size_t)Bq * Ss * Ee];            // 8 MiB
__device__ __half g_Kh[(size_t)Bq * Ss * Ee];            // 8 MiB
__device__ __half g_Ph[(size_t)Bq * Hh * Ss * Ss];       // 128 MiB probs [b][q][h][k]
__device__ __half g_xh[(size_t)Bq * Ss * Ee];            // 8 MiB
__device__ __half g_Wqh[Ee * Ee], g_Wkh[Ee * Ee], g_Woh[Ee * Ee];
__device__ uint32_t g_bm[(size_t)Bq * Ss * 32];          // 512 KiB mask bitmask

// ---------------------------------------------------------------------------
// PTX helpers (base compute_103 ISA only)
// ---------------------------------------------------------------------------
__device__ __forceinline__ uint32_t smem_u32(const void* p) {
    uint32_t a;
    asm("{ .reg .u64 t; cvta.to.shared.u64 t, %1; cvt.u32.u64 %0, t; }"
        : "=r"(a) : "l"(p));
    return a;
}
__device__ __forceinline__ void cp_async16(uint32_t saddr, const void* gaddr) {
    asm volatile("cp.async.cg.shared.global [%0], [%1], 16;"
                 :: "r"(saddr), "l"(gaddr) : "memory");
}
#define CP_COMMIT() asm volatile("cp.async.commit_group;" ::: "memory")
#define CP_WAIT(n)  asm volatile("cp.async.wait_group %0;" :: "n"(n) : "memory")

__device__ __forceinline__ void ldmat4(uint32_t& r0, uint32_t& r1,
                                       uint32_t& r2, uint32_t& r3, uint32_t addr) {
    asm volatile("ldmatrix.sync.aligned.m8n8.x4.shared.b16 {%0,%1,%2,%3}, [%4];"
                 : "=r"(r0), "=r"(r1), "=r"(r2), "=r"(r3) : "r"(addr));
}
__device__ __forceinline__ void mma_f16(float* c, const uint32_t* a, const uint32_t* b) {
    asm volatile(
        "mma.sync.aligned.m16n8k16.row.col.f32.f16.f16.f32 "
        "{%0,%1,%2,%3}, {%4,%5,%6,%7}, {%8,%9}, {%0,%1,%2,%3};"
        : "+f"(c[0]), "+f"(c[1]), "+f"(c[2]), "+f"(c[3])
        : "r"(a[0]), "r"(a[1]), "r"(a[2]), "r"(a[3]), "r"(b[0]), "r"(b[1]));
}

// ---------------------------------------------------------------------------
// FP16 GEMM-NT:  C[M,N] = A[M,K=1024] @ B[N,K]^T + bias[N]; all ld = 1024.
// 128x128 block tile, BK=64, 3-stage cp.async, 256 threads, 2 CTAs/SM.
// (Proven config: ~368us on the output GEMM. Byte-identical to round 15.)
// ---------------------------------------------------------------------------
#define BMt 128
#define BNt 128
#define BKt 64
#define NSTAGE 3
#define TILEB (128 * 128)
#define STAGE_BYTES (2 * TILEB)
#define GEMM_SMEM (NSTAGE * STAGE_BYTES)

__global__ __launch_bounds__(256, 2)
void gemm_f16(const __half* __restrict__ A, const __half* __restrict__ B,
              const float* __restrict__ bias, float* __restrict__ Cf,
              __half* __restrict__ Ch,
              const __half* __restrict__ B2, const float* __restrict__ bias2,
              __half* __restrict__ Ch2, int half_out) {
    extern __shared__ char sm[];
    __shared__ float s_bias[BNt];

    const int tid  = threadIdx.x;
    const int lane = tid & 31;
    const int wid  = tid >> 5;
    const int warp_m = wid >> 2;   // 0..1
    const int warp_n = wid & 3;    // 0..3
    const int bm = blockIdx.y * BMt;
    const int bn = blockIdx.x * BNt;

    if (blockIdx.z == 1) { B = B2; bias = bias2; Ch = Ch2; }

    if (tid < BNt) s_bias[tid] = bias[bn + tid];

    const uint32_t smb = smem_u32(sm);

    auto load_stage = [&](int c) {
        const int k0 = c * BKt;
        const uint32_t stg = smb + (c % NSTAGE) * STAGE_BYTES;
#pragma unroll
        for (int t = 0; t < 8; ++t) {
            const int idx = t * 256 + tid;
            const int region = idx >> 10;
            const int w = idx & 1023;
            const int r = w >> 3, cc = w & 7;
            const uint32_t so = stg + region * TILEB + r * 128
                              + ((cc ^ (r & 7)) << 4);
            const __half* src = region ? (B + (size_t)(bn + r) * Ee)
                                       : (A + (size_t)(bm + r) * Ee);
            cp_async16(so, src + k0 + cc * 8);
        }
        CP_COMMIT();
    };

    const int nk = Ee / BKt;   // 16
    for (int c = 0; c < NSTAGE - 1; ++c) load_stage(c);

    float acc[4][4][4];
#pragma unroll
    for (int mi = 0; mi < 4; ++mi)
#pragma unroll
        for (int ni = 0; ni < 4; ++ni)
#pragma unroll
            for (int j = 0; j < 4; ++j) acc[mi][ni][j] = 0.0f;

    const int tsub = (((lane >> 3) & 1) << 3) + (lane & 7);
    const int chof = lane >> 4;

    for (int c = 0; c < nk; ++c) {
        CP_WAIT(NSTAGE - 2);
        __syncthreads();
        if (c + NSTAGE - 1 < nk) load_stage(c + NSTAGE - 1);
        else CP_COMMIT();

        const uint32_t stgA = smb + (c % NSTAGE) * STAGE_BYTES;
        const uint32_t stgB = stgA + TILEB;
#pragma unroll
        for (int ks = 0; ks < 4; ++ks) {
            const int chunk = 2 * ks + chof;
            uint32_t a[4][4], b[4][2];
#pragma unroll
            for (int mi = 0; mi < 4; ++mi) {
                const int row = warp_m * 64 + mi * 16 + tsub;
                ldmat4(a[mi][0], a[mi][1], a[mi][2], a[mi][3],
                       stgA + row * 128 + ((chunk ^ (row & 7)) << 4));
            }
#pragma unroll
            for (int nf = 0; nf < 2; ++nf) {
                const int row = warp_n * 32 + nf * 16 + tsub;
                uint32_t q0, q1, q2, q3;
                ldmat4(q0, q1, q2, q3,
                       stgB + row * 128 + ((chunk ^ (row & 7)) << 4));
                b[nf * 2 + 0][0] = q0; b[nf * 2 + 0][1] = q2;
                b[nf * 2 + 1][0] = q1; b[nf * 2 + 1][1] = q3;
            }
#pragma unroll
            for (int mi = 0; mi < 4; ++mi)
#pragma unroll
                for (int ni = 0; ni < 4; ++ni)
                    mma_f16(acc[mi][ni], a[mi], b[ni]);
        }
    }

    // ---- epilogue ----
    const int r0 = lane >> 2;
    const int c0 = (lane & 3) * 2;
#pragma unroll
    for (int mi = 0; mi < 4; ++mi) {
        const int gr0 = bm + warp_m * 64 + mi * 16 + r0;
#pragma unroll
        for (int ni = 0; ni < 4; ++ni) {
            const int lc = warp_n * 32 + ni * 8 + c0;
            const int gc = bn + lc;
            const float b0 = s_bias[lc], b1 = s_bias[lc + 1];
            if (half_out) {
                __half2 h0, h1;
                h0.x = __float2half_rn(acc[mi][ni][0] + b0);
                h0.y = __float2half_rn(acc[mi][ni][1] + b1);
                h1.x = __float2half_rn(acc[mi][ni][2] + b0);
                h1.y = __float2half_rn(acc[mi][ni][3] + b1);
                *(__half2*)&Ch[(size_t)gr0 * Ee + gc]       = h0;
                *(__half2*)&Ch[(size_t)(gr0 + 8) * Ee + gc] = h1;
            } else {
                float2 v0, v1;
                v0.x = acc[mi][ni][0] + b0; v0.y = acc[mi][ni][1] + b1;
                v1.x = acc[mi][ni][2] + b0; v1.y = acc[mi][ni][3] + b1;
                *(float2*)&Cf[(size_t)gr0 * Ee + gc]       = v0;
                *(float2*)&Cf[(size_t)(gr0 + 8) * Ee + gc] = v1;
            }
        }
    }
}

// ---------------------------------------------------------------------------
// mask int32 -> bitmask. One warp per (row, word): bit k = mask[row][w*32+k]!=0.
// ---------------------------------------------------------------------------
__global__ void mask_to_bits(const int* __restrict__ mask) {
    const int gw = blockIdx.x * 8 + (threadIdx.x >> 5);
    const int lane = threadIdx.x & 31;
    const int row = gw >> 5, word = gw & 31;
    const int m = mask[(size_t)row * Ss + word * 32 + lane];
    const uint32_t bits = __ballot_sync(0xffffffffu, m != 0);
    if (lane == 0) g_bm[(size_t)row * 32 + word] = bits;
}

// ---------------------------------------------------------------------------
// Fused scores + mask + softmax, FQR=32 with smem P buffer (2 CTAs/SM).
// Per CTA: one (b,h), 32 q-rows x 1024 cols. K streamed once (8 chunks,
// 2-stage). Per chunk: MMA -> bitmask+exp -> unnormalized fp16 into smem P
// (row stride 2064B -> conflict-free). Final pass: scale by 1/rowsum (fp32),
// write coalesced fp16 to g_Ph. Mask read via 512KB L2-resident bitmask.
// ---------------------------------------------------------------------------
#define FQR 32
#define KST 16384
#define QOFF (2 * KST)                 // 32768
#define POFF (QOFF + 4096)             // 36864
#define PSTRIDE 2064
#define FUSED_SMEM (POFF + FQR * PSTRIDE)   // 102912

__global__ __launch_bounds__(256, 2)
void attn_fused(const int* __restrict__ mask_unused) {
    extern __shared__ char sm[];
    __shared__ float s_red[FQR][4];

    const int tid  = threadIdx.x;
    const int lane = tid & 31;
    const int wid  = tid >> 5;          // 0..7
    const int warp_m = wid >> 2;        // 0..1 : 16 q-rows
    const int warp_n = wid & 3;         // 0..3 : 32 cols per 128-chunk
    const int b  = blockIdx.y >> 4;
    const int h  = blockIdx.y & 15;
    const int q0 = blockIdx.x * FQR;

    const __half* Qg = g_Qh + ((size_t)(b * Ss + q0)) * Ee + h * DKk;
    const __half* Kg = g_Kh + (size_t)b * Ss * Ee + h * DKk;

    const uint32_t smb = smem_u32(sm);
    const int tsub = (((lane >> 3) & 1) << 3) + (lane & 7);
    const int chof = lane >> 4;

    // ---- Q strip: 32 rows x 64 halves (128B rows, swizzle c^(r&7)) ----
    {
        const int r = tid >> 3, c = tid & 7;
        cp_async16(smb + QOFF + r * 128 + ((c ^ (r & 7)) << 4),
                   Qg + (size_t)r * Ee + c * 8);
    }
    auto loadK = [&](int ch) {
        const uint32_t stg = smb + (ch & 1) * KST;
#pragma unroll
        for (int t = 0; t < 4; ++t) {
            const int idx = t * 256 + tid;
            const int r = idx >> 3, c = idx & 7;
            cp_async16(stg + r * 128 + ((c ^ (r & 7)) << 4),
                       Kg + (size_t)(ch * 128 + r) * Ee + c * 8);
        }
    };
    loadK(0); CP_COMMIT();      // group 0: Q + K0
    loadK(1); CP_COMMIT();

    uint32_t afr[4][4];
    float sum0 = 0.0f, sum1 = 0.0f;

    const int rr0 = warp_m * 16 + (lane >> 2);
    const int rr1 = rr0 + 8;
    const int c0 = (lane & 3) * 2;
    const uint32_t* bm0 = g_bm + ((size_t)(b * Ss + q0 + rr0)) * 32;
    const uint32_t* bm1 = g_bm + ((size_t)(b * Ss + q0 + rr1)) * 32;

#pragma unroll
    for (int ch = 0; ch < 8; ++ch) {
        CP_WAIT(1);
        __syncthreads();

        if (ch == 0) {
#pragma unroll
            for (int s = 0; s < 4; ++s) {
                const int row = warp_m * 16 + tsub;
                const int cc = 2 * s + chof;
                ldmat4(afr[s][0], afr[s][1], afr[s][2], afr[s][3],
                       smb + QOFF + row * 128 + ((cc ^ (row & 7)) << 4));
            }
        }

        const uint32_t stg = smb + (ch & 1) * KST;
        float acc[4][4];
#pragma unroll
        for (int ni = 0; ni < 4; ++ni)
#pragma unroll
            for (int j = 0; j < 4; ++j) acc[ni][j] = 0.0f;

#pragma unroll
        for (int s = 0; s < 4; ++s) {
            const int cc = 2 * s + chof;
            uint32_t bfr[4][2];
#pragma unroll
            for (int nf = 0; nf < 2; ++nf) {
                const int rowB = warp_n * 32 + nf * 16 + tsub;
                uint32_t v0, v1, v2, v3;
                ldmat4(v0, v1, v2, v3,
                       stg + rowB * 128 + ((cc ^ (rowB & 7)) << 4));
                bfr[nf * 2 + 0][0] = v0; bfr[nf * 2 + 0][1] = v2;
                bfr[nf * 2 + 1][0] = v1; bfr[nf * 2 + 1][1] = v3;
            }
#pragma unroll
            for (int ni = 0; ni < 4; ++ni)
                mma_f16(acc[ni], afr[s], bfr[ni]);
        }

        // ---- bitmask -> exp (unnormalized) -> sums -> smem P ----
        const uint32_t w0 = bm0[ch * 4 + warp_n];
        const uint32_t w1 = bm1[ch * 4 + warp_n];
#pragma unroll
        for (int ni = 0; ni < 4; ++ni) {
            const int bit = ni * 8 + c0;
            float* v = acc[ni];
            v[0] = ((w0 >> bit) & 1u)       ? __expf(v[0] * 0.125f) : 0.0f;
            v[1] = ((w0 >> (bit + 1)) & 1u) ? __expf(v[1] * 0.125f) : 0.0f;
            v[2] = ((w1 >> bit) & 1u)       ? __expf(v[2] * 0.125f) : 0.0f;
            v[3] = ((w1 >> (bit + 1)) & 1u) ? __expf(v[3] * 0.125f) : 0.0f;
            sum0 += v[0] + v[1];
            sum1 += v[2] + v[3];
            const int col = ch * 128 + warp_n * 32 + ni * 8 + c0;
            __half2 o0, o1;
            o0.x = __float2half_rn(v[0]); o0.y = __float2half_rn(v[1]);
            o1.x = __float2half_rn(v[2]); o1.y = __float2half_rn(v[3]);
            *(__half2*)(sm + POFF + rr0 * PSTRIDE + col * 2) = o0;
            *(__half2*)(sm + POFF + rr1 * PSTRIDE + col * 2) = o1;
        }

        __syncthreads();                 // buffer (ch&1) free for reuse
        if (ch + 2 < 8) loadK(ch + 2);
        CP_COMMIT();
    }

    // ---- row sums -> s_red ----
    sum0 += __shfl_xor_sync(0xffffffffu, sum0, 1);
    sum0 += __shfl_xor_sync(0xffffffffu, sum0, 2);
    sum1 += __shfl_xor_sync(0xffffffffu, sum1, 1);
    sum1 += __shfl_xor_sync(0xffffffffu, sum1, 2);
    if ((lane & 3) == 0) { s_red[rr0][warp_n] = sum0; s_red[rr1][warp_n] = sum1; }
    __syncthreads();

    // ---- normalize + coalesced store: warp w handles rows 4w..4w+3 ----
#pragma unroll
    for (int rl = 0; rl < 4; ++rl) {
        const int row = wid * 4 + rl;
        const float inv = 1.0f / (s_red[row][0] + s_red[row][1]
                                + s_red[row][2] + s_red[row][3]);
        const char* src = sm + POFF + row * PSTRIDE;
        __half* dst = g_Ph + ((size_t)((b * Ss + q0 + row) * Hh + h)) * Ss;
#pragma unroll
        for (int j = 0; j < 4; ++j) {
            const int e = (j * 32 + lane) * 8;     // element index (8 halves/txn)
            uint4 pk = *(const uint4*)(src + e * 2);
            const __half2* hp = (const __half2*)&pk;
            uint4 outpk;
            __half2* op = (__half2*)&outpk;
#pragma unroll
            for (int q = 0; q < 4; ++q) {
                float2 f = __half22float2(hp[q]);
                op[q].x = __float2half_rn(f.x * inv);
                op[q].y = __float2half_rn(f.y * inv);
            }
            *(uint4*)(dst + e) = outpk;
        }
    }
}

// ---------------------------------------------------------------------------
// Merged fp32 -> fp16 (rn) conversion. grid.y 0..3 = quarters of x, 4..6 = W's.
// ---------------------------------------------------------------------------
__global__ void conv_f16_all(const float4* __restrict__ x, __half2* __restrict__ xh,
                             const float4* __restrict__ wq, __half2* __restrict__ wqh,
                             const float4* __restrict__ wk, __half2* __restrict__ wkh,
                             const float4* __restrict__ wo, __half2* __restrict__ woh) {
    const int seg = blockIdx.y;
    const int i0 = blockIdx.x * blockDim.x + threadIdx.x;
    const float4* s; __half2* d;
    if (seg < 4)      { s = x  + (size_t)seg * 262144; d = xh  + (size_t)seg * 524288; }
    else if (seg == 4){ s = wq; d = wqh; }
    else if (seg == 5){ s = wk; d = wkh; }
    else              { s = wo; d = woh; }
#pragma unroll
    for (int t = 0; t < 2; ++t) {
        const int i = i0 + t * 131072;
        const float4 v = s[i];
        __half2 h0, h1;
        h0.x = __float2half_rn(v.x); h0.y = __float2half_rn(v.y);
        h1.x = __float2half_rn(v.z); h1.y = __float2half_rn(v.w);
        d[i * 2 + 0] = h0;
        d[i * 2 + 1] = h1;
    }
}

// ---------------------------------------------------------------------------
extern "C" void kernel_launch(void* const* d_in, const int* in_sizes, int n_in,
                              void* d_out, int out_size) {
    const float* x   = (const float*)d_in[0];
    const int*   msk = (const int*)  d_in[1];
    const float* Wq  = (const float*)d_in[2];
    const float* bq  = (const float*)d_in[3];
    const float* Wk  = (const float*)d_in[4];
    const float* bk  = (const float*)d_in[5];
    // d_in[6], d_in[7] = Wv, bv : unused (reference discards V)
    const float* Wo  = (const float*)d_in[8];
    const float* bo  = (const float*)d_in[9];
    float* out = (float*)d_out;

    __half *qh, *kh, *ph, *xh, *wqh, *wkh, *woh;
    cudaGetSymbolAddress((void**)&qh,  g_Qh);
    cudaGetSymbolAddress((void**)&kh,  g_Kh);
    cudaGetSymbolAddress((void**)&ph,  g_Ph);
    cudaGetSymbolAddress((void**)&xh,  g_xh);
    cudaGetSymbolAddress((void**)&wqh, g_Wqh);
    cudaGetSymbolAddress((void**)&wkh, g_Wkh);
    cudaGetSymbolAddress((void**)&woh, g_Woh);

    cudaFuncSetAttribute(gemm_f16,
                         cudaFuncAttributeMaxDynamicSharedMemorySize, GEMM_SMEM);
    cudaFuncSetAttribute(attn_fused,
                         cudaFuncAttributeMaxDynamicSharedMemorySize, FUSED_SMEM);

    // 0a) mask -> bitmask (independent; tiny)
    {
        mask_to_bits<<<(Bq * Ss * 32) / 8, 256>>>(msk);
    }
    // 0b) fp32 -> fp16 conversion (one launch, 2 float4/thread)
    {
        dim3 grid(512, 7);
        conv_f16_all<<<grid, 256>>>((const float4*)x,  (__half2*)xh,
                                    (const float4*)Wq, (__half2*)wqh,
                                    (const float4*)Wk, (__half2*)wkh,
                                    (const float4*)Wo, (__half2*)woh);
    }

    // 1) Q + K projections in ONE launch (z=0 -> Q, z=1 -> K), fp16 outputs
    {
        dim3 grid(Ee / BNt, (Bq * Ss) / BMt, 2);   // (8, 32, 2)
        gemm_f16<<<grid, 256, GEMM_SMEM>>>(xh, wqh, bq, nullptr, qh,
                                           wkh, bk, kh, 1);
    }

    // 2) Fused scores + bitmask + softmax -> g_Ph (fp16), 2 CTAs/SM, FQR=32
    {
        dim3 grid(Ss / FQR, Bq * Hh);              // (32, 64)
        attn_fused<<<grid, 256, FUSED_SMEM>>>(msk);
    }

    // 3) Output projection: P[65536,1024] @ Wo^T + bo -> fp32 out
    {
        const int M = Bq * Ss * Hh;                // 65536
        dim3 grid(Ee / BNt, M / BMt, 1);           // (8, 512)
        gemm_f16<<<grid, 256, GEMM_SMEM>>>(ph, woh, bo, out, nullptr,
                                           woh, bo, nullptr, 0);
    }
}